// round 7
// baseline (speedup 1.0000x reference)
#include <cuda_runtime.h>

// ---------------------------------------------------------------------------
// Fused spatio-temporal GCN, one 256-thread CTA per (b,t), 1 CTA/SM.
// Stage 3 tiles are 6 rows x 16 cols per thread with the m-reduction split
// across two thread-halves (keeps 8 warps); cross-half reduce via smem.
// All GEMM operands in smem (cp.async prefetched); packed fma.rn.f32x2.
// ---------------------------------------------------------------------------

#define Bq   16
#define FINq 3
#define NV   170
#define MPAD 176          // cheb row pad / V row count (16B rows, m-halves 88/88)
#define HALFM 88
#define TMP  68           // Tm row pad (16B rows, conflict-safe)
#define TTq  288
#define HH   64
#define OO   64
#define KK   3
#define RPT  6            // rows per thread

typedef unsigned long long ull;

__device__ __forceinline__ ull f2fma(ull a, ull b, ull c) {
    ull d;
    asm("fma.rn.f32x2 %0, %1, %2, %3;" : "=l"(d) : "l"(a), "l"(b), "l"(c));
    return d;
}
__device__ __forceinline__ ull f2add(ull a, ull b) {
    ull d;
    asm("add.rn.f32x2 %0, %1, %2;" : "=l"(d) : "l"(a), "l"(b));
    return d;
}
__device__ __forceinline__ ull f2dup(float a) {
    ull d;
    asm("mov.b64 %0, {%1, %1};" : "=l"(d) : "f"(a));
    return d;
}
__device__ __forceinline__ float2 f2un(ull p) {
    float2 r;
    asm("mov.b64 {%0, %1}, %2;" : "=f"(r.x), "=f"(r.y) : "l"(p));
    return r;
}
__device__ __forceinline__ unsigned s2u(const void* p) {
    unsigned a;
    asm("{ .reg .u64 t; cvta.to.shared.u64 t, %1; cvt.u32.u64 %0, t; }"
        : "=r"(a) : "l"(p));
    return a;
}
#define CPA16(d, s) asm volatile("cp.async.cg.shared.global [%0], [%1], 16;" \
                                 :: "r"(d), "l"(s) : "memory")
#define CPCOMMIT()  asm volatile("cp.async.commit_group;" ::: "memory")
#define CPWAIT(n)   asm volatile("cp.async.wait_group %0;" :: "n"(n) : "memory")

// transposed cheb, m padded 170->176 with zeros: [k][n][m]
__device__ __align__(16) float g_chebT[KK * NV * MPAD];

__global__ void prep_chebT(const float* __restrict__ cheb) {
    int idx = blockIdx.x * 256 + threadIdx.x;
    if (idx >= KK * NV * MPAD) return;
    int j  = idx % MPAD;
    int kn = idx / MPAD;
    g_chebT[idx] = (j < NV) ? cheb[kn * NV + j] : 0.0f;
}

// shared memory layout (float offsets)
#define WC_OFF   0                        // conv_w 576
#define WCB_OFF  576                      // conv_b 64
#define WRES_OFF 640                      // res_w 192
#define WRB_OFF  832                      // res_b 64
#define CHS_OFF  896                      // cheb slice 170*176 = 29920
#define XS_OFF   896                      // x slice 1530 (overlaps chs; moved
                                          //  to regs before cheb[0] lands)
#define TM_OFF   (CHS_OFF + NV * MPAD)    // 30816; Tm[m][TMP] 170*68 = 11560
#define V_OFF    (TM_OFF + NV * TMP)      // 42376; V[176][64] = 11264
#define THS_OFF  (V_OFF + MPAD * OO)      // 53640; thetaS 4096
#define SMEM_FLOATS (THS_OFF + HH * OO)   // 57736
#define SMEM_BYTES  (SMEM_FLOATS * 4)     // 230944 B (<= 232448)

#define CHEB_CHUNKS  ((NV * MPAD) / 4)    // 7480 x 16B
#define THETA_CHUNKS ((HH * OO) / 4)      // 1024 x 16B

__global__ void __launch_bounds__(256, 1)
stgcn_fused_kernel(const float* __restrict__ x,
                   const float* __restrict__ theta,
                   const float* __restrict__ conv_w,
                   const float* __restrict__ conv_b,
                   const float* __restrict__ res_w,
                   const float* __restrict__ res_b,
                   float* __restrict__ out)
{
    extern __shared__ float sm[];
    float* wc   = sm + WC_OFF;
    float* wcb  = sm + WCB_OFF;
    float* wres = sm + WRES_OFF;
    float* wrb  = sm + WRB_OFF;
    float* xs   = sm + XS_OFF;
    float* chs  = sm + CHS_OFF;
    float* Tm   = sm + TM_OFF;
    float* Vv   = sm + V_OFF;
    float* ths  = sm + THS_OFF;
    const unsigned ths_u = s2u(ths);
    const unsigned chs_u = s2u(chs);

    const int t   = blockIdx.x;
    const int b   = blockIdx.y;
    const int tid = threadIdx.x;

    // ---- prefetch theta[0] ----
    for (int i = tid; i < THETA_CHUNKS; i += 256)
        CPA16(ths_u + i * 16, theta + (size_t)i * 4);
    CPCOMMIT();

    // ---------------- stage 0: xs + small weights + V pad-rows zero ----------------
    for (int i = tid; i < FINq * 3 * NV; i += 256) {
        int f = i / (3 * NV);
        int r = i - f * (3 * NV);
        int s = r / NV;
        int m = r - s * NV;
        int tt = t + s - 1;
        float v = 0.0f;
        if (tt >= 0 && tt < TTq)
            v = x[((size_t)(b * FINq + f) * NV + m) * TTq + tt];
        xs[i] = v;                       // (f*3+s)*NV + m
    }
    for (int i = tid; i < HH * FINq * 3; i += 256) wc[i] = conv_w[i];
    for (int i = tid; i < OO * FINq;     i += 256) wres[i] = res_w[i];
    for (int i = tid; i < (MPAD - NV) * OO; i += 256) Vv[NV * OO + i] = 0.0f;
    if (tid < HH)                    wcb[tid]      = conv_b[tid];
    else if (tid >= 64 && tid < 128) wrb[tid - 64] = res_b[tid - 64];
    __syncthreads();

    // ---------------- stage 1: temporal conv + ReLU -> Tm[m][c] ----------------
    for (int idx = tid; idx < NV * HH; idx += 256) {
        int m = idx >> 6;
        int c = idx & 63;
        float v = wcb[c];
        #pragma unroll
        for (int f = 0; f < FINq; ++f)
            #pragma unroll
            for (int s = 0; s < 3; ++s)
                v = fmaf(xs[(f * 3 + s) * NV + m], wc[(c * FINq + f) * 3 + s], v);
        Tm[m * TMP + c] = fmaxf(v, 0.0f);
    }

    // mappings: row-group shared; stage2 uses 8 o-cols, stage3 uses 16 + m-half
    const int g    = tid >> 3;           // 0..31
    const int n0   = g * RPT;
    const bool act = (n0 < NV);          // g <= 28
    const int o8   = (tid & 7) * 8;      // stage 2
    const int o16  = (tid & 3) * 16;     // stage 3
    const int half = (tid >> 2) & 1;     // stage 3 m-half
    const int mb   = half * HALFM;

    int nr[RPT];
    #pragma unroll
    for (int i = 0; i < RPT; ++i) nr[i] = (n0 + i < NV) ? (n0 + i) : (NV - 1);

    // snapshot residual x into registers (xs region recycled for chs)
    float xr[RPT][3];
    #pragma unroll
    for (int i = 0; i < RPT; ++i) {
        xr[i][0] = xs[1 * NV + nr[i]];
        xr[i][1] = xs[4 * NV + nr[i]];
        xr[i][2] = xs[7 * NV + nr[i]];
    }
    __syncthreads();     // xs reads + Tm writes done

    // ---- prefetch cheb[0] into chs (overwrites xs region) ----
    for (int i = tid; i < CHEB_CHUNKS; i += 256)
        CPA16(chs_u + i * 16, g_chebT + (size_t)i * 4);
    CPCOMMIT();
    CPWAIT(1);           // theta[0] landed
    __syncthreads();

    ull acc[RPT][8];
    #pragma unroll
    for (int i = 0; i < RPT; ++i)
        #pragma unroll
        for (int p = 0; p < 8; ++p) acc[i][p] = 0ull;

    for (int k = 0; k < KK; ++k) {
        // ------------- stage 2: V = Tm @ thetaS (tile 6x8 at o8) -------------
        if (act) {
            ull a2[RPT][4];
            #pragma unroll
            for (int i = 0; i < RPT; ++i)
                #pragma unroll
                for (int p = 0; p < 4; ++p) a2[i][p] = 0ull;

            for (int c = 0; c < HH; c += 4) {
                ulonglong2 th0a = *(const ulonglong2*)(ths + (c + 0) * OO + o8);
                ulonglong2 th0b = *(const ulonglong2*)(ths + (c + 0) * OO + o8 + 4);
                ulonglong2 th1a = *(const ulonglong2*)(ths + (c + 1) * OO + o8);
                ulonglong2 th1b = *(const ulonglong2*)(ths + (c + 1) * OO + o8 + 4);
                ulonglong2 th2a = *(const ulonglong2*)(ths + (c + 2) * OO + o8);
                ulonglong2 th2b = *(const ulonglong2*)(ths + (c + 2) * OO + o8 + 4);
                ulonglong2 th3a = *(const ulonglong2*)(ths + (c + 3) * OO + o8);
                ulonglong2 th3b = *(const ulonglong2*)(ths + (c + 3) * OO + o8 + 4);
                #pragma unroll
                for (int i = 0; i < RPT; ++i) {
                    ulonglong2 tm4 = *(const ulonglong2*)(Tm + nr[i] * TMP + c);
                    float2 t01 = f2un(tm4.x);
                    float2 t23 = f2un(tm4.y);
                    ull d0 = f2dup(t01.x), d1 = f2dup(t01.y);
                    ull d2 = f2dup(t23.x), d3 = f2dup(t23.y);
                    a2[i][0] = f2fma(d0, th0a.x, a2[i][0]);
                    a2[i][1] = f2fma(d0, th0a.y, a2[i][1]);
                    a2[i][2] = f2fma(d0, th0b.x, a2[i][2]);
                    a2[i][3] = f2fma(d0, th0b.y, a2[i][3]);
                    a2[i][0] = f2fma(d1, th1a.x, a2[i][0]);
                    a2[i][1] = f2fma(d1, th1a.y, a2[i][1]);
                    a2[i][2] = f2fma(d1, th1b.x, a2[i][2]);
                    a2[i][3] = f2fma(d1, th1b.y, a2[i][3]);
                    a2[i][0] = f2fma(d2, th2a.x, a2[i][0]);
                    a2[i][1] = f2fma(d2, th2a.y, a2[i][1]);
                    a2[i][2] = f2fma(d2, th2b.x, a2[i][2]);
                    a2[i][3] = f2fma(d2, th2b.y, a2[i][3]);
                    a2[i][0] = f2fma(d3, th3a.x, a2[i][0]);
                    a2[i][1] = f2fma(d3, th3a.y, a2[i][1]);
                    a2[i][2] = f2fma(d3, th3b.x, a2[i][2]);
                    a2[i][3] = f2fma(d3, th3b.y, a2[i][3]);
                }
            }
            #pragma unroll
            for (int i = 0; i < RPT; ++i) {
                int m = n0 + i;
                if (m < NV) {
                    ulonglong2* dst = (ulonglong2*)(Vv + (size_t)m * OO + o8);
                    dst[0] = make_ulonglong2(a2[i][0], a2[i][1]);
                    dst[1] = make_ulonglong2(a2[i][2], a2[i][3]);
                }
            }
        }
        CPWAIT(0);          // chs[k] landed
        __syncthreads();    // V + chs visible to all

        // prefetch theta[k+1] (covered by stage 3)
        if (k < KK - 1) {
            const float* tsrc = theta + (size_t)(k + 1) * HH * OO;
            for (int i = tid; i < THETA_CHUNKS; i += 256)
                CPA16(ths_u + i * 16, tsrc + (size_t)i * 4);
            CPCOMMIT();
        }

        // ------------- stage 3: acc += chs[n][m-half] * V[m-half][o16..+16) -------------
        if (act) {
            const float* cr0 = chs + (size_t)nr[0] * MPAD + mb;
            const float* cr1 = chs + (size_t)nr[1] * MPAD + mb;
            const float* cr2 = chs + (size_t)nr[2] * MPAD + mb;
            const float* cr3 = chs + (size_t)nr[3] * MPAD + mb;
            const float* cr4 = chs + (size_t)nr[4] * MPAD + mb;
            const float* cr5 = chs + (size_t)nr[5] * MPAD + mb;
            #pragma unroll 2
            for (int mm = 0; mm < HALFM; mm += 4) {
                ulonglong2 cb[RPT];
                cb[0] = *(const ulonglong2*)(cr0 + mm);
                cb[1] = *(const ulonglong2*)(cr1 + mm);
                cb[2] = *(const ulonglong2*)(cr2 + mm);
                cb[3] = *(const ulonglong2*)(cr3 + mm);
                cb[4] = *(const ulonglong2*)(cr4 + mm);
                cb[5] = *(const ulonglong2*)(cr5 + mm);
                const float* vp = Vv + (size_t)(mb + mm) * OO + o16;
                #pragma unroll
                for (int r = 0; r < 4; ++r) {
                    ulonglong2 va = *(const ulonglong2*)(vp + r * OO);
                    ulonglong2 vb = *(const ulonglong2*)(vp + r * OO + 4);
                    ulonglong2 vc = *(const ulonglong2*)(vp + r * OO + 8);
                    ulonglong2 vd = *(const ulonglong2*)(vp + r * OO + 12);
                    #pragma unroll
                    for (int i = 0; i < RPT; ++i) {
                        float2 clo = f2un(cb[i].x);
                        float2 chi = f2un(cb[i].y);
                        float cs = (r == 0) ? clo.x : (r == 1) ? clo.y
                                 : (r == 2) ? chi.x : chi.y;
                        ull d = f2dup(cs);
                        acc[i][0] = f2fma(d, va.x, acc[i][0]);
                        acc[i][1] = f2fma(d, va.y, acc[i][1]);
                        acc[i][2] = f2fma(d, vb.x, acc[i][2]);
                        acc[i][3] = f2fma(d, vb.y, acc[i][3]);
                        acc[i][4] = f2fma(d, vc.x, acc[i][4]);
                        acc[i][5] = f2fma(d, vc.y, acc[i][5]);
                        acc[i][6] = f2fma(d, vd.x, acc[i][6]);
                        acc[i][7] = f2fma(d, vd.y, acc[i][7]);
                    }
                }
            }
        }
        __syncthreads();    // chs readers done before overwrite

        if (k < KK - 1) {
            const float* csrc = g_chebT + (size_t)(k + 1) * NV * MPAD;
            for (int i = tid; i < CHEB_CHUNKS; i += 256)
                CPA16(chs_u + i * 16, csrc + (size_t)i * 4);
            CPCOMMIT();
            CPWAIT(1);      // theta[k+1] ready (cheb[k+1] still in flight)
            __syncthreads();
        }
    }

    // ---------------- cross-half reduction (chs region now free) ----------------
    if (act && half == 1) {
        #pragma unroll
        for (int i = 0; i < RPT; ++i) {
            ulonglong2* dst = (ulonglong2*)(chs + (size_t)nr[i] * OO + o16);
            dst[0] = make_ulonglong2(acc[i][0], acc[i][1]);
            dst[1] = make_ulonglong2(acc[i][2], acc[i][3]);
            dst[2] = make_ulonglong2(acc[i][4], acc[i][5]);
            dst[3] = make_ulonglong2(acc[i][6], acc[i][7]);
        }
    }
    __syncthreads();

    // ---------------- epilogue (half 0): add partner, relu + residual ----------------
    if (act && half == 0) {
        #pragma unroll
        for (int i = 0; i < RPT; ++i) {
            int n = n0 + i;
            if (n >= NV) break;
            const ulonglong2* src = (const ulonglong2*)(chs + (size_t)nr[i] * OO + o16);
            ulonglong2 p0 = src[0], p1 = src[1], p2 = src[2], p3 = src[3];
            acc[i][0] = f2add(acc[i][0], p0.x);
            acc[i][1] = f2add(acc[i][1], p0.y);
            acc[i][2] = f2add(acc[i][2], p1.x);
            acc[i][3] = f2add(acc[i][3], p1.y);
            acc[i][4] = f2add(acc[i][4], p2.x);
            acc[i][5] = f2add(acc[i][5], p2.y);
            acc[i][6] = f2add(acc[i][6], p3.x);
            acc[i][7] = f2add(acc[i][7], p3.y);
            #pragma unroll
            for (int p = 0; p < 8; ++p) {
                float2 gv = f2un(acc[i][p]);
                int o0 = o16 + 2 * p;
                float r0 = wrb[o0] + xr[i][0] * wres[o0 * 3 + 0]
                                   + xr[i][1] * wres[o0 * 3 + 1]
                                   + xr[i][2] * wres[o0 * 3 + 2];
                float r1 = wrb[o0 + 1] + xr[i][0] * wres[(o0 + 1) * 3 + 0]
                                       + xr[i][1] * wres[(o0 + 1) * 3 + 1]
                                       + xr[i][2] * wres[(o0 + 1) * 3 + 2];
                out[((size_t)(b * OO + o0)     * NV + n) * TTq + t] = fmaxf(gv.x, 0.0f) + r0;
                out[((size_t)(b * OO + o0 + 1) * NV + n) * TTq + t] = fmaxf(gv.y, 0.0f) + r1;
            }
        }
    }
}

extern "C" void kernel_launch(void* const* d_in, const int* in_sizes, int n_in,
                              void* d_out, int out_size)
{
    (void)in_sizes; (void)n_in; (void)out_size;
    const float* x      = (const float*)d_in[0];
    // d_in[1] = adj (unused by forward)
    const float* cheb   = (const float*)d_in[2];
    const float* conv_w = (const float*)d_in[3];
    const float* conv_b = (const float*)d_in[4];
    const float* theta  = (const float*)d_in[5];
    const float* res_w  = (const float*)d_in[6];
    const float* res_b  = (const float*)d_in[7];
    float* out = (float*)d_out;

    prep_chebT<<<(KK * NV * MPAD + 255) / 256, 256>>>(cheb);

    cudaFuncSetAttribute(stgcn_fused_kernel,
                         cudaFuncAttributeMaxDynamicSharedMemorySize, SMEM_BYTES);

    dim3 grid(TTq, Bq);   // 4608 CTAs, one per (b, t)
    stgcn_fused_kernel<<<grid, 256, SMEM_BYTES>>>(
        x, theta, conv_w, conv_b, res_w, res_b, out);
}

// round 9
// speedup vs baseline: 1.3571x; 1.3571x over previous
#include <cuda_runtime.h>

// ---------------------------------------------------------------------------
// Fused spatio-temporal GCN, ONE 512-thread CTA per (b,t), 1 CTA/SM (16 warps).
// Small per-thread tiles (stage2 3x8, stage3 6x4) keep regs <= 128 so all 16
// warps are resident; smem holds all GEMM operands (cp.async prefetched).
// ---------------------------------------------------------------------------

#define FINq 3
#define NV   170
#define CPAD 172          // cheb col pad (zeros at 170..171); 6*172%32=8 -> row spread
#define TMP  68           // Tm row pad (16B rows)
#define TTq  288
#define HH   64
#define OO   64
#define KK   3
#define NT   512

typedef unsigned long long ull;

__device__ __forceinline__ ull f2fma(ull a, ull b, ull c) {
    ull d;
    asm("fma.rn.f32x2 %0, %1, %2, %3;" : "=l"(d) : "l"(a), "l"(b), "l"(c));
    return d;
}
__device__ __forceinline__ ull f2dup(float a) {
    ull d;
    asm("mov.b64 %0, {%1, %1};" : "=l"(d) : "f"(a));
    return d;
}
__device__ __forceinline__ float2 f2un(ull p) {
    float2 r;
    asm("mov.b64 {%0, %1}, %2;" : "=f"(r.x), "=f"(r.y) : "l"(p));
    return r;
}
__device__ __forceinline__ unsigned s2u(const void* p) {
    unsigned a;
    asm("{ .reg .u64 t; cvta.to.shared.u64 t, %1; cvt.u32.u64 %0, t; }"
        : "=r"(a) : "l"(p));
    return a;
}
#define CPA16(d, s) asm volatile("cp.async.cg.shared.global [%0], [%1], 16;" \
                                 :: "r"(d), "l"(s) : "memory")
#define CPCOMMIT()  asm volatile("cp.async.commit_group;" ::: "memory")
#define CPWAIT(n)   asm volatile("cp.async.wait_group %0;" :: "n"(n) : "memory")

// transposed cheb [k][n][m], m zero-padded 170->172
__device__ __align__(16) float g_chebT[KK * NV * CPAD];

__global__ void prep_chebT(const float* __restrict__ cheb) {
    int idx = blockIdx.x * 256 + threadIdx.x;
    if (idx >= KK * NV * CPAD) return;
    int j  = idx % CPAD;
    int kn = idx / CPAD;
    g_chebT[idx] = (j < NV) ? cheb[kn * NV + j] : 0.0f;
}

// shared memory layout (float offsets)
#define WC_OFF   0                        // conv_w 576
#define WCB_OFF  576                      // conv_b 64
#define WRES_OFF 640                      // res_w 192
#define WRB_OFF  832                      // res_b 64
#define CHS_OFF  896                      // cheb slice 170*172 = 29240
#define XS_OFF   896                      // x slice 1530 (overlaps chs; consumed
                                          //  before cheb[0] lands)
#define TM_OFF   (CHS_OFF + NV * CPAD)    // 30136; Tm[m][68] = 11560
#define V_OFF    (TM_OFF + NV * TMP)      // 41696; V[172][64] = 11008 (2 pad rows)
#define THS_OFF  (V_OFF + 172 * OO)       // 52704; thetaS 4096
#define SMEM_FLOATS (THS_OFF + HH * OO)   // 56800
#define SMEM_BYTES  (SMEM_FLOATS * 4)     // 227200 B (<= 232448)

#define CHEB_CHUNKS  ((NV * CPAD) / 4)    // 7310 x 16B
#define THETA_CHUNKS ((HH * OO) / 4)      // 1024 x 16B

__global__ void __launch_bounds__(NT, 1)
stgcn_fused_kernel(const float* __restrict__ x,
                   const float* __restrict__ theta,
                   const float* __restrict__ conv_w,
                   const float* __restrict__ conv_b,
                   const float* __restrict__ res_w,
                   const float* __restrict__ res_b,
                   float* __restrict__ out)
{
    extern __shared__ float sm[];
    float* wc   = sm + WC_OFF;
    float* wcb  = sm + WCB_OFF;
    float* wres = sm + WRES_OFF;
    float* wrb  = sm + WRB_OFF;
    float* xs   = sm + XS_OFF;
    float* chs  = sm + CHS_OFF;
    float* Tm   = sm + TM_OFF;
    float* Vv   = sm + V_OFF;
    float* ths  = sm + THS_OFF;
    const unsigned ths_u = s2u(ths);
    const unsigned chs_u = s2u(chs);

    const int t   = blockIdx.x;
    const int b   = blockIdx.y;
    const int tid = threadIdx.x;

    // ---- prefetch theta[0] (group committed FIRST) ----
    for (int i = tid; i < THETA_CHUNKS; i += NT)
        CPA16(ths_u + i * 16, theta + (size_t)i * 4);
    CPCOMMIT();

    // ---------------- stage 0: xs + small weights + V pad rows ----------------
    for (int i = tid; i < FINq * 3 * NV; i += NT) {
        int f = i / (3 * NV);
        int r = i - f * (3 * NV);
        int s = r / NV;
        int m = r - s * NV;
        int tt = t + s - 1;
        float v = 0.0f;
        if (tt >= 0 && tt < TTq)
            v = x[((size_t)(b * FINq + f) * NV + m) * TTq + tt];
        xs[i] = v;                       // (f*3+s)*NV + m
    }
    for (int i = tid; i < HH * FINq * 3; i += NT) wc[i] = conv_w[i];
    if (tid < OO * FINq)                 wres[tid]       = res_w[tid];
    else if (tid >= 192 && tid < 256)    wcb[tid - 192]  = conv_b[tid - 192];
    else if (tid >= 256 && tid < 320)    wrb[tid - 256]  = res_b[tid - 256];
    else if (tid >= 320 && tid < 448)    Vv[NV * OO + (tid - 320)] = 0.0f; // rows 170,171
    __syncthreads();

    // ---------------- stage 1: temporal conv + ReLU -> Tm[m][c] ----------------
    for (int idx = tid; idx < NV * HH; idx += NT) {
        int m = idx >> 6;
        int c = idx & 63;
        float v = wcb[c];
        #pragma unroll
        for (int f = 0; f < FINq; ++f)
            #pragma unroll
            for (int s = 0; s < 3; ++s)
                v = fmaf(xs[(f * 3 + s) * NV + m], wc[(c * FINq + f) * 3 + s], v);
        Tm[m * TMP + c] = fmaxf(v, 0.0f);
    }

    // ---- thread mappings ----
    // stage 2: 3 rows x 8 cols ; stage 3: 6 rows x 4 cols
    const int og8 = (tid & 7) * 8;       // stage 2 col base
    const int g2  = tid >> 3;            // 0..63, active g2 < 57
    const int m20 = g2 * 3;
    const bool act2 = (m20 < NV);

    const int o4  = (tid & 15) * 4;      // stage 3 col base
    const int g3  = tid >> 4;            // 0..31, active g3 < 29
    const int n0  = g3 * 6;
    const bool act3 = (n0 < NV);

    int nr[6];
    #pragma unroll
    for (int i = 0; i < 6; ++i) nr[i] = (n0 + i < NV) ? (n0 + i) : (NV - 1);

    // snapshot residual x (center tap) before xs region is recycled
    float xr0[6], xr1[6], xr2[6];
    if (act3) {
        #pragma unroll
        for (int i = 0; i < 6; ++i) {
            xr0[i] = xs[1 * NV + nr[i]];
            xr1[i] = xs[4 * NV + nr[i]];
            xr2[i] = xs[7 * NV + nr[i]];
        }
    }
    __syncthreads();     // xs reads + Tm writes done

    // ---- prefetch cheb[0] into chs (overwrites xs region) ----
    for (int i = tid; i < CHEB_CHUNKS; i += NT)
        CPA16(chs_u + i * 16, g_chebT + (size_t)i * 4);
    CPCOMMIT();
    CPWAIT(1);           // theta[0] landed
    __syncthreads();

    ull acc[6][2];
    #pragma unroll
    for (int i = 0; i < 6; ++i) { acc[i][0] = 0ull; acc[i][1] = 0ull; }

    for (int k = 0; k < KK; ++k) {
        // ------------- stage 2: V = Tm @ thetaS (3x8 tiles) -------------
        if (act2) {
            int mr[3];
            #pragma unroll
            for (int i = 0; i < 3; ++i) mr[i] = (m20 + i < NV) ? (m20 + i) : (NV - 1);
            ull a2[3][4];
            #pragma unroll
            for (int i = 0; i < 3; ++i)
                #pragma unroll
                for (int p = 0; p < 4; ++p) a2[i][p] = 0ull;

            for (int c = 0; c < HH; c += 4) {
                ulonglong2 th0a = *(const ulonglong2*)(ths + (c + 0) * OO + og8);
                ulonglong2 th0b = *(const ulonglong2*)(ths + (c + 0) * OO + og8 + 4);
                ulonglong2 th1a = *(const ulonglong2*)(ths + (c + 1) * OO + og8);
                ulonglong2 th1b = *(const ulonglong2*)(ths + (c + 1) * OO + og8 + 4);
                ulonglong2 th2a = *(const ulonglong2*)(ths + (c + 2) * OO + og8);
                ulonglong2 th2b = *(const ulonglong2*)(ths + (c + 2) * OO + og8 + 4);
                ulonglong2 th3a = *(const ulonglong2*)(ths + (c + 3) * OO + og8);
                ulonglong2 th3b = *(const ulonglong2*)(ths + (c + 3) * OO + og8 + 4);
                #pragma unroll
                for (int i = 0; i < 3; ++i) {
                    ulonglong2 tm4 = *(const ulonglong2*)(Tm + mr[i] * TMP + c);
                    float2 t01 = f2un(tm4.x);
                    float2 t23 = f2un(tm4.y);
                    ull d0 = f2dup(t01.x), d1 = f2dup(t01.y);
                    ull d2 = f2dup(t23.x), d3 = f2dup(t23.y);
                    a2[i][0] = f2fma(d0, th0a.x, a2[i][0]);
                    a2[i][1] = f2fma(d0, th0a.y, a2[i][1]);
                    a2[i][2] = f2fma(d0, th0b.x, a2[i][2]);
                    a2[i][3] = f2fma(d0, th0b.y, a2[i][3]);
                    a2[i][0] = f2fma(d1, th1a.x, a2[i][0]);
                    a2[i][1] = f2fma(d1, th1a.y, a2[i][1]);
                    a2[i][2] = f2fma(d1, th1b.x, a2[i][2]);
                    a2[i][3] = f2fma(d1, th1b.y, a2[i][3]);
                    a2[i][0] = f2fma(d2, th2a.x, a2[i][0]);
                    a2[i][1] = f2fma(d2, th2a.y, a2[i][1]);
                    a2[i][2] = f2fma(d2, th2b.x, a2[i][2]);
                    a2[i][3] = f2fma(d2, th2b.y, a2[i][3]);
                    a2[i][0] = f2fma(d3, th3a.x, a2[i][0]);
                    a2[i][1] = f2fma(d3, th3a.y, a2[i][1]);
                    a2[i][2] = f2fma(d3, th3b.x, a2[i][2]);
                    a2[i][3] = f2fma(d3, th3b.y, a2[i][3]);
                }
            }
            #pragma unroll
            for (int i = 0; i < 3; ++i) {
                int m = m20 + i;
                if (m < NV) {
                    ulonglong2* dst = (ulonglong2*)(Vv + (size_t)m * OO + og8);
                    dst[0] = make_ulonglong2(a2[i][0], a2[i][1]);
                    dst[1] = make_ulonglong2(a2[i][2], a2[i][3]);
                }
            }
        }
        CPWAIT(0);          // chs[k] landed
        __syncthreads();    // V + chs visible to all

        // prefetch theta[k+1] (covered by stage 3)
        if (k < KK - 1) {
            const float* tsrc = theta + (size_t)(k + 1) * HH * OO;
            for (int i = tid; i < THETA_CHUNKS; i += NT)
                CPA16(ths_u + i * 16, tsrc + (size_t)i * 4);
            CPCOMMIT();
        }

        // ------------- stage 3: acc += chs[n][m] * V[m][o4..o4+4) -------------
        if (act3) {
            const float* cr0 = chs + (size_t)nr[0] * CPAD;
            const float* cr1 = chs + (size_t)nr[1] * CPAD;
            const float* cr2 = chs + (size_t)nr[2] * CPAD;
            const float* cr3 = chs + (size_t)nr[3] * CPAD;
            const float* cr4 = chs + (size_t)nr[4] * CPAD;
            const float* cr5 = chs + (size_t)nr[5] * CPAD;
            #pragma unroll 1
            for (int m = 0; m < CPAD; m += 4) {   // cols 170,171 are zero in chs
                float4 c0 = *(const float4*)(cr0 + m);
                float4 c1 = *(const float4*)(cr1 + m);
                float4 c2 = *(const float4*)(cr2 + m);
                float4 c3 = *(const float4*)(cr3 + m);
                float4 c4 = *(const float4*)(cr4 + m);
                float4 c5 = *(const float4*)(cr5 + m);
                const float* vp = Vv + (size_t)m * OO + o4;
                ulonglong2 v0 = *(const ulonglong2*)(vp);
                ulonglong2 v1 = *(const ulonglong2*)(vp + OO);
                ulonglong2 v2 = *(const ulonglong2*)(vp + 2 * OO);
                ulonglong2 v3 = *(const ulonglong2*)(vp + 3 * OO);
                ull d;
                d = f2dup(c0.x); acc[0][0] = f2fma(d, v0.x, acc[0][0]); acc[0][1] = f2fma(d, v0.y, acc[0][1]);
                d = f2dup(c1.x); acc[1][0] = f2fma(d, v0.x, acc[1][0]); acc[1][1] = f2fma(d, v0.y, acc[1][1]);
                d = f2dup(c2.x); acc[2][0] = f2fma(d, v0.x, acc[2][0]); acc[2][1] = f2fma(d, v0.y, acc[2][1]);
                d = f2dup(c3.x); acc[3][0] = f2fma(d, v0.x, acc[3][0]); acc[3][1] = f2fma(d, v0.y, acc[3][1]);
                d = f2dup(c4.x); acc[4][0] = f2fma(d, v0.x, acc[4][0]); acc[4][1] = f2fma(d, v0.y, acc[4][1]);
                d = f2dup(c5.x); acc[5][0] = f2fma(d, v0.x, acc[5][0]); acc[5][1] = f2fma(d, v0.y, acc[5][1]);
                d = f2dup(c0.y); acc[0][0] = f2fma(d, v1.x, acc[0][0]); acc[0][1] = f2fma(d, v1.y, acc[0][1]);
                d = f2dup(c1.y); acc[1][0] = f2fma(d, v1.x, acc[1][0]); acc[1][1] = f2fma(d, v1.y, acc[1][1]);
                d = f2dup(c2.y); acc[2][0] = f2fma(d, v1.x, acc[2][0]); acc[2][1] = f2fma(d, v1.y, acc[2][1]);
                d = f2dup(c3.y); acc[3][0] = f2fma(d, v1.x, acc[3][0]); acc[3][1] = f2fma(d, v1.y, acc[3][1]);
                d = f2dup(c4.y); acc[4][0] = f2fma(d, v1.x, acc[4][0]); acc[4][1] = f2fma(d, v1.y, acc[4][1]);
                d = f2dup(c5.y); acc[5][0] = f2fma(d, v1.x, acc[5][0]); acc[5][1] = f2fma(d, v1.y, acc[5][1]);
                d = f2dup(c0.z); acc[0][0] = f2fma(d, v2.x, acc[0][0]); acc[0][1] = f2fma(d, v2.y, acc[0][1]);
                d = f2dup(c1.z); acc[1][0] = f2fma(d, v2.x, acc[1][0]); acc[1][1] = f2fma(d, v2.y, acc[1][1]);
                d = f2dup(c2.z); acc[2][0] = f2fma(d, v2.x, acc[2][0]); acc[2][1] = f2fma(d, v2.y, acc[2][1]);
                d = f2dup(c3.z); acc[3][0] = f2fma(d, v2.x, acc[3][0]); acc[3][1] = f2fma(d, v2.y, acc[3][1]);
                d = f2dup(c4.z); acc[4][0] = f2fma(d, v2.x, acc[4][0]); acc[4][1] = f2fma(d, v2.y, acc[4][1]);
                d = f2dup(c5.z); acc[5][0] = f2fma(d, v2.x, acc[5][0]); acc[5][1] = f2fma(d, v2.y, acc[5][1]);
                d = f2dup(c0.w); acc[0][0] = f2fma(d, v3.x, acc[0][0]); acc[0][1] = f2fma(d, v3.y, acc[0][1]);
                d = f2dup(c1.w); acc[1][0] = f2fma(d, v3.x, acc[1][0]); acc[1][1] = f2fma(d, v3.y, acc[1][1]);
                d = f2dup(c2.w); acc[2][0] = f2fma(d, v3.x, acc[2][0]); acc[2][1] = f2fma(d, v3.y, acc[2][1]);
                d = f2dup(c3.w); acc[3][0] = f2fma(d, v3.x, acc[3][0]); acc[3][1] = f2fma(d, v3.y, acc[3][1]);
                d = f2dup(c4.w); acc[4][0] = f2fma(d, v3.x, acc[4][0]); acc[4][1] = f2fma(d, v3.y, acc[4][1]);
                d = f2dup(c5.w); acc[5][0] = f2fma(d, v3.x, acc[5][0]); acc[5][1] = f2fma(d, v3.y, acc[5][1]);
            }
        }
        __syncthreads();    // chs readers done before overwrite

        if (k < KK - 1) {
            const float* csrc = g_chebT + (size_t)(k + 1) * NV * CPAD;
            for (int i = tid; i < CHEB_CHUNKS; i += NT)
                CPA16(chs_u + i * 16, csrc + (size_t)i * 4);
            CPCOMMIT();
            CPWAIT(1);      // theta[k+1] ready (cheb[k+1] still in flight)
            __syncthreads();
        }
    }

    // ---------------- epilogue: relu(gcn) + residual ----------------
    if (act3) {
        #pragma unroll
        for (int i = 0; i < 6; ++i) {
            int n = n0 + i;
            if (n >= NV) break;
            #pragma unroll
            for (int p = 0; p < 2; ++p) {
                float2 gv = f2un(acc[i][p]);
                int o0 = o4 + 2 * p;
                float r0 = wrb[o0] + xr0[i] * wres[o0 * 3 + 0]
                                   + xr1[i] * wres[o0 * 3 + 1]
                                   + xr2[i] * wres[o0 * 3 + 2];
                float r1 = wrb[o0 + 1] + xr0[i] * wres[(o0 + 1) * 3 + 0]
                                       + xr1[i] * wres[(o0 + 1) * 3 + 1]
                                       + xr2[i] * wres[(o0 + 1) * 3 + 2];
                out[((size_t)(b * OO + o0)     * NV + n) * TTq + t] = fmaxf(gv.x, 0.0f) + r0;
                out[((size_t)(b * OO + o0 + 1) * NV + n) * TTq + t] = fmaxf(gv.y, 0.0f) + r1;
            }
        }
    }
}

extern "C" void kernel_launch(void* const* d_in, const int* in_sizes, int n_in,
                              void* d_out, int out_size)
{
    (void)in_sizes; (void)n_in; (void)out_size;
    const float* x      = (const float*)d_in[0];
    // d_in[1] = adj (unused by forward)
    const float* cheb   = (const float*)d_in[2];
    const float* conv_w = (const float*)d_in[3];
    const float* conv_b = (const float*)d_in[4];
    const float* theta  = (const float*)d_in[5];
    const float* res_w  = (const float*)d_in[6];
    const float* res_b  = (const float*)d_in[7];
    float* out = (float*)d_out;

    prep_chebT<<<(KK * NV * CPAD + 255) / 256, 256>>>(cheb);

    cudaFuncSetAttribute(stgcn_fused_kernel,
                         cudaFuncAttributeMaxDynamicSharedMemorySize, SMEM_BYTES);

    dim3 grid(TTq, 16);   // 4608 CTAs, one per (b, t)
    stgcn_fused_kernel<<<grid, NT, SMEM_BYTES>>>(
        x, theta, conv_w, conv_b, res_w, res_b, out);
}

// round 10
// speedup vs baseline: 1.4952x; 1.1018x over previous
#include <cuda_runtime.h>

// ---------------------------------------------------------------------------
// Fused spatio-temporal GCN, one 256-thread CTA per (b,t), 1 CTA/SM.
// Stage-3 tile: 12 rows x 8 cols per thread (0.83 smem-lane-bytes per MAC),
// 2-way m-split with halves in SEPARATE warps; cross-half reduce via smem.
// All operands in smem, cp.async double-pumped; packed fma.rn.f32x2 math.
// ---------------------------------------------------------------------------

#define FINq 3
#define NV   170
#define CPAD 172          // cheb col pad (zeros at 170,171)
#define TMP  68           // Tm row pad (16B rows)
#define TTq  288
#define HH   64
#define OO   64
#define KK   3
#define NT   256
#define R3   12           // stage3 rows/thread (15 groups x 12 = 180)
#define NR3  180
#define R2   6            // stage2 rows/thread (29 groups x 6 = 174)

typedef unsigned long long ull;

__device__ __forceinline__ ull f2fma(ull a, ull b, ull c) {
    ull d;
    asm("fma.rn.f32x2 %0, %1, %2, %3;" : "=l"(d) : "l"(a), "l"(b), "l"(c));
    return d;
}
__device__ __forceinline__ ull f2add(ull a, ull b) {
    ull d;
    asm("add.rn.f32x2 %0, %1, %2;" : "=l"(d) : "l"(a), "l"(b));
    return d;
}
__device__ __forceinline__ ull f2dup(float a) {
    ull d;
    asm("mov.b64 %0, {%1, %1};" : "=l"(d) : "f"(a));
    return d;
}
__device__ __forceinline__ float2 f2un(ull p) {
    float2 r;
    asm("mov.b64 {%0, %1}, %2;" : "=f"(r.x), "=f"(r.y) : "l"(p));
    return r;
}
__device__ __forceinline__ unsigned s2u(const void* p) {
    unsigned a;
    asm("{ .reg .u64 t; cvta.to.shared.u64 t, %1; cvt.u32.u64 %0, t; }"
        : "=r"(a) : "l"(p));
    return a;
}
#define CPA16(d, s) asm volatile("cp.async.cg.shared.global [%0], [%1], 16;" \
                                 :: "r"(d), "l"(s) : "memory")
#define CPCOMMIT()  asm volatile("cp.async.commit_group;" ::: "memory")
#define CPWAIT(n)   asm volatile("cp.async.wait_group %0;" :: "n"(n) : "memory")

// transposed cheb [k][n][m], m zero-padded to 172
__device__ __align__(16) float g_chebT[KK * NV * CPAD];

__global__ void prep_chebT(const float* __restrict__ cheb) {
    int idx = blockIdx.x * 256 + threadIdx.x;
    if (idx >= KK * NV * CPAD) return;
    int j  = idx % CPAD;
    int kn = idx / CPAD;
    g_chebT[idx] = (j < NV) ? cheb[kn * NV + j] : 0.0f;
}

// shared memory layout (float offsets)
#define WC_OFF   0                        // conv_w 576
#define WCB_OFF  576                      // conv_b 64
#define WRES_OFF 640                      // res_w 192
#define WRB_OFF  832                      // res_b 64
#define XRES_OFF 896                      // residual x taps 3*170=510 (pad 512)
#define CHS_OFF  1408                     // cheb slice 170*172 = 29240
#define XS_OFF   1408                     // x slice 1530 (overlaps chs)
#define TM_OFF   (CHS_OFF + NV * CPAD)    // 30648; Tm[m][68] 170*68 = 11560
#define V_OFF    (TM_OFF + NV * TMP)      // 42208; V[172][64] = 11008
#define THS_OFF  (V_OFF + CPAD * OO)      // 53216; thetaS 4096
#define SMEM_FLOATS (THS_OFF + HH * OO)   // 57312
#define SMEM_BYTES  (SMEM_FLOATS * 4)     // 229248 B (<= 232448)

#define CHEB_CHUNKS  ((NV * CPAD) / 4)    // 7310 x 16B
#define THETA_CHUNKS ((HH * OO) / 4)      // 1024 x 16B

__global__ void __launch_bounds__(NT, 1)
stgcn_fused_kernel(const float* __restrict__ x,
                   const float* __restrict__ theta,
                   const float* __restrict__ conv_w,
                   const float* __restrict__ conv_b,
                   const float* __restrict__ res_w,
                   const float* __restrict__ res_b,
                   float* __restrict__ out)
{
    extern __shared__ float sm[];
    float* wc   = sm + WC_OFF;
    float* wcb  = sm + WCB_OFF;
    float* wres = sm + WRES_OFF;
    float* wrb  = sm + WRB_OFF;
    float* xres = sm + XRES_OFF;
    float* xs   = sm + XS_OFF;
    float* chs  = sm + CHS_OFF;
    float* Tm   = sm + TM_OFF;
    float* Vv   = sm + V_OFF;
    float* ths  = sm + THS_OFF;
    const unsigned ths_u = s2u(ths);
    const unsigned chs_u = s2u(chs);

    const int t   = blockIdx.x;
    const int b   = blockIdx.y;
    const int tid = threadIdx.x;

    // ---- prefetch theta[0] ----
    for (int i = tid; i < THETA_CHUNKS; i += NT)
        CPA16(ths_u + i * 16, theta + (size_t)i * 4);
    CPCOMMIT();

    // ---------------- stage 0: xs + small weights ----------------
    for (int i = tid; i < FINq * 3 * NV; i += NT) {
        int f = i / (3 * NV);
        int r = i - f * (3 * NV);
        int s = r / NV;
        int m = r - s * NV;
        int tt = t + s - 1;
        float v = 0.0f;
        if (tt >= 0 && tt < TTq)
            v = x[((size_t)(b * FINq + f) * NV + m) * TTq + tt];
        xs[i] = v;                       // (f*3+s)*NV + m
    }
    for (int i = tid; i < HH * FINq * 3; i += NT) wc[i] = conv_w[i];
    if (tid < OO * FINq)              wres[tid]      = res_w[tid];
    else if (tid >= 192 && tid < 256) wcb[tid - 192] = conv_b[tid - 192];
    if (tid < OO)                     wrb[tid]       = res_b[tid];
    __syncthreads();

    // ---------------- stage 1: temporal conv + ReLU -> Tm[m][c] ----------------
    for (int idx = tid; idx < NV * HH; idx += NT) {
        int m = idx >> 6;
        int c = idx & 63;
        float v = wcb[c];
        #pragma unroll
        for (int f = 0; f < FINq; ++f)
            #pragma unroll
            for (int s = 0; s < 3; ++s)
                v = fmaf(xs[(f * 3 + s) * NV + m], wc[(c * FINq + f) * 3 + s], v);
        Tm[m * TMP + c] = fmaxf(v, 0.0f);
    }
    // save residual x center taps before xs region is recycled for cheb
    for (int i = tid; i < FINq * NV; i += NT) {
        int f = i / NV;
        int n = i - f * NV;
        xres[i] = xs[(f * 3 + 1) * NV + n];
    }
    __syncthreads();     // all xs reads + Tm writes done

    // ---- prefetch cheb[0] (overwrites xs region) ----
    for (int i = tid; i < CHEB_CHUNKS; i += NT)
        CPA16(chs_u + i * 16, g_chebT + (size_t)i * 4);
    CPCOMMIT();
    CPWAIT(1);           // theta[0] landed
    __syncthreads();

    // ---- thread mappings ----
    // stage 2: 6 rows x 8 cols, 29 groups
    const int o8s2 = (tid & 7) * 8;
    const int rg2  = tid >> 3;           // 0..31
    const int m20  = rg2 * R2;
    const bool act2 = (m20 < NV);        // rg2 <= 28

    // stage 3: 12 rows x 8 cols, m-split in 2 HALVES mapped to separate warps
    const int half = tid >> 7;           // warps 0-3: half 0, warps 4-7: half 1
    const int htid = tid & 127;
    const int o8   = (htid & 7) * 8;
    const int rg3  = htid >> 3;          // 0..15
    const int n0   = rg3 * R3;
    const bool act3 = (rg3 < 15);        // 120 threads per half
    const int mlo  = half ? 88 : 0;
    const int mhi  = half ? CPAD : 88;   // 22 / 21 quads

    int croff[R3];
    #pragma unroll
    for (int i = 0; i < R3; ++i) {
        int n = n0 + i;
        croff[i] = ((n < NV) ? n : (NV - 1)) * CPAD;
    }

    ull acc[R3][4];
    #pragma unroll
    for (int i = 0; i < R3; ++i)
        #pragma unroll
        for (int p = 0; p < 4; ++p) acc[i][p] = 0ull;

    for (int k = 0; k < KK; ++k) {
        // ------------- stage 2: V = Tm @ thetaS (6x8 tiles) -------------
        if (act2) {
            int mr[R2];
            #pragma unroll
            for (int i = 0; i < R2; ++i)
                mr[i] = (m20 + i < NV) ? (m20 + i) : (NV - 1);
            ull a2[R2][4];
            #pragma unroll
            for (int i = 0; i < R2; ++i)
                #pragma unroll
                for (int p = 0; p < 4; ++p) a2[i][p] = 0ull;

            for (int c = 0; c < HH; c += 4) {
                ulonglong2 th0a = *(const ulonglong2*)(ths + (c + 0) * OO + o8s2);
                ulonglong2 th0b = *(const ulonglong2*)(ths + (c + 0) * OO + o8s2 + 4);
                ulonglong2 th1a = *(const ulonglong2*)(ths + (c + 1) * OO + o8s2);
                ulonglong2 th1b = *(const ulonglong2*)(ths + (c + 1) * OO + o8s2 + 4);
                ulonglong2 th2a = *(const ulonglong2*)(ths + (c + 2) * OO + o8s2);
                ulonglong2 th2b = *(const ulonglong2*)(ths + (c + 2) * OO + o8s2 + 4);
                ulonglong2 th3a = *(const ulonglong2*)(ths + (c + 3) * OO + o8s2);
                ulonglong2 th3b = *(const ulonglong2*)(ths + (c + 3) * OO + o8s2 + 4);
                #pragma unroll
                for (int i = 0; i < R2; ++i) {
                    ulonglong2 tm4 = *(const ulonglong2*)(Tm + mr[i] * TMP + c);
                    float2 t01 = f2un(tm4.x);
                    float2 t23 = f2un(tm4.y);
                    ull d0 = f2dup(t01.x), d1 = f2dup(t01.y);
                    ull d2 = f2dup(t23.x), d3 = f2dup(t23.y);
                    a2[i][0] = f2fma(d0, th0a.x, a2[i][0]);
                    a2[i][1] = f2fma(d0, th0a.y, a2[i][1]);
                    a2[i][2] = f2fma(d0, th0b.x, a2[i][2]);
                    a2[i][3] = f2fma(d0, th0b.y, a2[i][3]);
                    a2[i][0] = f2fma(d1, th1a.x, a2[i][0]);
                    a2[i][1] = f2fma(d1, th1a.y, a2[i][1]);
                    a2[i][2] = f2fma(d1, th1b.x, a2[i][2]);
                    a2[i][3] = f2fma(d1, th1b.y, a2[i][3]);
                    a2[i][0] = f2fma(d2, th2a.x, a2[i][0]);
                    a2[i][1] = f2fma(d2, th2a.y, a2[i][1]);
                    a2[i][2] = f2fma(d2, th2b.x, a2[i][2]);
                    a2[i][3] = f2fma(d2, th2b.y, a2[i][3]);
                    a2[i][0] = f2fma(d3, th3a.x, a2[i][0]);
                    a2[i][1] = f2fma(d3, th3a.y, a2[i][1]);
                    a2[i][2] = f2fma(d3, th3b.x, a2[i][2]);
                    a2[i][3] = f2fma(d3, th3b.y, a2[i][3]);
                }
            }
            #pragma unroll
            for (int i = 0; i < R2; ++i) {
                int m = m20 + i;
                if (m < CPAD) {          // rows 170,171 hold junk x 0-cheb = ok
                    ulonglong2* dst = (ulonglong2*)(Vv + (size_t)m * OO + o8s2);
                    dst[0] = make_ulonglong2(a2[i][0], a2[i][1]);
                    dst[1] = make_ulonglong2(a2[i][2], a2[i][3]);
                }
            }
        }
        CPWAIT(0);          // chs[k] landed
        __syncthreads();    // V + chs visible

        if (k < KK - 1) {   // theta[k+1] prefetch rides under stage 3
            const float* tsrc = theta + (size_t)(k + 1) * HH * OO;
            for (int i = tid; i < THETA_CHUNKS; i += NT)
                CPA16(ths_u + i * 16, tsrc + (size_t)i * 4);
            CPCOMMIT();
        }

        // ------------- stage 3: acc += chs[n][m] * V[m][o8..+8), half m-range ----
        if (act3) {
            #pragma unroll 1
            for (int m = mlo; m < mhi; m += 4) {
                float4 cb[R3];
                #pragma unroll
                for (int i = 0; i < R3; ++i)
                    cb[i] = *(const float4*)(chs + croff[i] + m);
                const float* vp = Vv + (size_t)m * OO + o8;
                #pragma unroll
                for (int r = 0; r < 4; ++r) {
                    ulonglong2 va = *(const ulonglong2*)(vp + r * OO);
                    ulonglong2 vb = *(const ulonglong2*)(vp + r * OO + 4);
                    #pragma unroll
                    for (int i = 0; i < R3; ++i) {
                        float cs = (r == 0) ? cb[i].x : (r == 1) ? cb[i].y
                                 : (r == 2) ? cb[i].z : cb[i].w;
                        ull d = f2dup(cs);
                        acc[i][0] = f2fma(d, va.x, acc[i][0]);
                        acc[i][1] = f2fma(d, va.y, acc[i][1]);
                        acc[i][2] = f2fma(d, vb.x, acc[i][2]);
                        acc[i][3] = f2fma(d, vb.y, acc[i][3]);
                    }
                }
            }
        }
        __syncthreads();    // chs readers done before overwrite

        if (k < KK - 1) {
            const float* csrc = g_chebT + (size_t)(k + 1) * NV * CPAD;
            for (int i = tid; i < CHEB_CHUNKS; i += NT)
                CPA16(chs_u + i * 16, csrc + (size_t)i * 4);
            CPCOMMIT();
            CPWAIT(1);      // theta[k+1] ready (cheb[k+1] in flight)
            __syncthreads();
        }
    }

    // ---------------- cross-half reduce via chs region (now free) ----------------
    if (act3 && half == 1) {
        #pragma unroll
        for (int i = 0; i < R3; ++i) {
            ulonglong2* dst = (ulonglong2*)(chs + (size_t)(n0 + i) * OO + o8);
            dst[0] = make_ulonglong2(acc[i][0], acc[i][1]);
            dst[1] = make_ulonglong2(acc[i][2], acc[i][3]);
        }
    }
    __syncthreads();

    // ---------------- epilogue (half 0): add partner, relu + residual ----------------
    if (act3 && half == 0) {
        #pragma unroll
        for (int i = 0; i < R3; ++i) {
            int n = n0 + i;
            if (n >= NV) break;
            const ulonglong2* src = (const ulonglong2*)(chs + (size_t)n * OO + o8);
            ulonglong2 p0 = src[0], p1 = src[1];
            acc[i][0] = f2add(acc[i][0], p0.x);
            acc[i][1] = f2add(acc[i][1], p0.y);
            acc[i][2] = f2add(acc[i][2], p1.x);
            acc[i][3] = f2add(acc[i][3], p1.y);
            float x0 = xres[n];
            float x1 = xres[NV + n];
            float x2 = xres[2 * NV + n];
            #pragma unroll
            for (int p = 0; p < 4; ++p) {
                float2 gv = f2un(acc[i][p]);
                int o0 = o8 + 2 * p;
                float r0 = wrb[o0] + x0 * wres[o0 * 3 + 0]
                                   + x1 * wres[o0 * 3 + 1]
                                   + x2 * wres[o0 * 3 + 2];
                float r1 = wrb[o0 + 1] + x0 * wres[(o0 + 1) * 3 + 0]
                                       + x1 * wres[(o0 + 1) * 3 + 1]
                                       + x2 * wres[(o0 + 1) * 3 + 2];
                out[((size_t)(b * OO + o0)     * NV + n) * TTq + t] = fmaxf(gv.x, 0.0f) + r0;
                out[((size_t)(b * OO + o0 + 1) * NV + n) * TTq + t] = fmaxf(gv.y, 0.0f) + r1;
            }
        }
    }
}

extern "C" void kernel_launch(void* const* d_in, const int* in_sizes, int n_in,
                              void* d_out, int out_size)
{
    (void)in_sizes; (void)n_in; (void)out_size;
    const float* x      = (const float*)d_in[0];
    // d_in[1] = adj (unused by forward)
    const float* cheb   = (const float*)d_in[2];
    const float* conv_w = (const float*)d_in[3];
    const float* conv_b = (const float*)d_in[4];
    const float* theta  = (const float*)d_in[5];
    const float* res_w  = (const float*)d_in[6];
    const float* res_b  = (const float*)d_in[7];
    float* out = (float*)d_out;

    prep_chebT<<<(KK * NV * CPAD + 255) / 256, 256>>>(cheb);

    cudaFuncSetAttribute(stgcn_fused_kernel,
                         cudaFuncAttributeMaxDynamicSharedMemorySize, SMEM_BYTES);

    dim3 grid(TTq, 16);   // 4608 CTAs, one per (b, t)
    stgcn_fused_kernel<<<grid, NT, SMEM_BYTES>>>(
        x, theta, conv_w, conv_b, res_w, res_b, out);
}